// round 5
// baseline (speedup 1.0000x reference)
#include <cuda_runtime.h>
#include <math.h>

#define T_TOK 8192
#define D_DIM 1024
#define E_NUM 8
#define IMOE  1024
#define ISH   4096

// Scratch (device globals: allocation-free per harness rules)
__device__ float g_he[(size_t)E_NUM * T_TOK * IMOE];   // 256 MB expert hidden
__device__ float g_hsh[(size_t)T_TOK * ISH];           // 128 MB shared hidden
__device__ int   g_cnt[E_NUM];
__device__ int   g_tok[E_NUM * T_TOK];
__device__ float g_wt [E_NUM * T_TOK];
__device__ float g_sgate[T_TOK];

__global__ void zero_counts_kernel() {
    if (threadIdx.x < E_NUM) g_cnt[threadIdx.x] = 0;
}

// One warp per token: logits, top-2 routing, shared-gate sigmoid.
__global__ void router_kernel(const float* __restrict__ x,
                              const float* __restrict__ gw,
                              const float* __restrict__ sgw,
                              float* __restrict__ logits_out) {
    int t = (int)((blockIdx.x * blockDim.x + threadIdx.x) >> 5);
    int lane = threadIdx.x & 31;
    if (t >= T_TOK) return;
    const float* xr = x + (size_t)t * D_DIM;
    float acc[E_NUM];
#pragma unroll
    for (int e = 0; e < E_NUM; e++) acc[e] = 0.f;
    float sg = 0.f;
    for (int k = lane; k < D_DIM; k += 32) {
        float xv = xr[k];
#pragma unroll
        for (int e = 0; e < E_NUM; e++) acc[e] = fmaf(xv, gw[k * E_NUM + e], acc[e]);
        sg = fmaf(xv, sgw[k], sg);
    }
#pragma unroll
    for (int o = 16; o; o >>= 1) {
#pragma unroll
        for (int e = 0; e < E_NUM; e++) acc[e] += __shfl_xor_sync(0xffffffffu, acc[e], o);
        sg += __shfl_xor_sync(0xffffffffu, sg, o);
    }
    if (lane == 0) {
        float m = acc[0];
#pragma unroll
        for (int e = 1; e < E_NUM; e++) m = fmaxf(m, acc[e]);
        float p[E_NUM];
#pragma unroll
        for (int e = 0; e < E_NUM; e++) {
            p[e] = expf(acc[e] - m);
            logits_out[t * E_NUM + e] = acc[e];
        }
        // top-2 (lowest index wins ties, matching lax.top_k)
        int i0 = 0;
#pragma unroll
        for (int e = 1; e < E_NUM; e++) if (p[e] > p[i0]) i0 = e;
        int i1 = (i0 == 0) ? 1 : 0;
#pragma unroll
        for (int e = 0; e < E_NUM; e++) if (e != i0 && e != i1 && p[e] > p[i1]) i1 = e;
        // need lowest-index tie handling for i1 too: redo scan cleanly
        i1 = -1;
        float best = -1.f;
#pragma unroll
        for (int e = 0; e < E_NUM; e++) {
            if (e == i0) continue;
            if (p[e] > best) { best = p[e]; i1 = e; }
        }
        float s = p[i0] + p[i1];
        float w0 = p[i0] / s, w1 = p[i1] / s;
        int p0 = atomicAdd(&g_cnt[i0], 1);
        g_tok[i0 * T_TOK + p0] = t; g_wt[i0 * T_TOK + p0] = w0;
        int p1 = atomicAdd(&g_cnt[i1], 1);
        g_tok[i1 * T_TOK + p1] = t; g_wt[i1 * T_TOK + p1] = w1;
        g_sgate[t] = 1.f / (1.f + expf(-sg));
    }
}

// ---------------- Shared expert: up/gate fused SGEMM ----------------
// C tile 64x64, K-tile 16, 256 threads, 4x4 per-thread microtile, dual-B.
__global__ __launch_bounds__(256) void shared_up_kernel(
        const float* __restrict__ x,
        const float* __restrict__ Bg,
        const float* __restrict__ Bu) {
    int m0 = blockIdx.y * 64;
    int n0 = blockIdx.x * 64;
    __shared__ float As[16][64], Bgs[16][64], Bus[16][64];
    int tid = threadIdx.x;
    int tx = tid & 15, ty = tid >> 4;
    int arow = tid >> 2, akq = tid & 3;
    int brow = tid >> 4, bnq = tid & 15;
    const float* Ap  = x  + (size_t)(m0 + arow) * D_DIM + akq * 4;
    const float* Bgp = Bg + (size_t)brow * ISH + n0 + bnq * 4;
    const float* Bup = Bu + (size_t)brow * ISH + n0 + bnq * 4;
    float accG[4][4], accU[4][4];
#pragma unroll
    for (int i = 0; i < 4; i++)
#pragma unroll
        for (int j = 0; j < 4; j++) { accG[i][j] = 0.f; accU[i][j] = 0.f; }

    for (int k0 = 0; k0 < D_DIM; k0 += 16) {
        float4 av = *(const float4*)(Ap + k0);
        As[akq * 4 + 0][arow] = av.x; As[akq * 4 + 1][arow] = av.y;
        As[akq * 4 + 2][arow] = av.z; As[akq * 4 + 3][arow] = av.w;
        *(float4*)&Bgs[brow][bnq * 4] = *(const float4*)(Bgp + (size_t)k0 * ISH);
        *(float4*)&Bus[brow][bnq * 4] = *(const float4*)(Bup + (size_t)k0 * ISH);
        __syncthreads();
#pragma unroll
        for (int kk = 0; kk < 16; kk++) {
            float4 a4 = *(const float4*)&As[kk][ty * 4];
            float4 g4 = *(const float4*)&Bgs[kk][tx * 4];
            float4 u4 = *(const float4*)&Bus[kk][tx * 4];
            float ar[4] = {a4.x, a4.y, a4.z, a4.w};
            float gr[4] = {g4.x, g4.y, g4.z, g4.w};
            float ur[4] = {u4.x, u4.y, u4.z, u4.w};
#pragma unroll
            for (int i = 0; i < 4; i++)
#pragma unroll
                for (int j = 0; j < 4; j++) {
                    accG[i][j] = fmaf(ar[i], gr[j], accG[i][j]);
                    accU[i][j] = fmaf(ar[i], ur[j], accU[i][j]);
                }
        }
        __syncthreads();
    }
#pragma unroll
    for (int i = 0; i < 4; i++) {
        int row = m0 + ty * 4 + i;
#pragma unroll
        for (int j = 0; j < 4; j++) {
            float g = accG[i][j], u = accU[i][j];
            float h = (g / (1.f + expf(-g))) * u;
            g_hsh[(size_t)row * ISH + n0 + tx * 4 + j] = h;
        }
    }
}

// Shared down: g_hsh[8192,4096] @ sd[4096,1024], scaled by sgate, plain-store.
__global__ __launch_bounds__(256) void shared_down_kernel(
        const float* __restrict__ B,
        float* __restrict__ out) {
    int m0 = blockIdx.y * 64;
    int n0 = blockIdx.x * 64;
    __shared__ float As[16][64], Bs[16][64];
    int tid = threadIdx.x;
    int tx = tid & 15, ty = tid >> 4;
    int arow = tid >> 2, akq = tid & 3;
    int brow = tid >> 4, bnq = tid & 15;
    const float* Ap = g_hsh + (size_t)(m0 + arow) * ISH + akq * 4;
    const float* Bp = B + (size_t)brow * D_DIM + n0 + bnq * 4;
    float acc[4][4];
#pragma unroll
    for (int i = 0; i < 4; i++)
#pragma unroll
        for (int j = 0; j < 4; j++) acc[i][j] = 0.f;

    for (int k0 = 0; k0 < ISH; k0 += 16) {
        float4 av = *(const float4*)(Ap + k0);
        As[akq * 4 + 0][arow] = av.x; As[akq * 4 + 1][arow] = av.y;
        As[akq * 4 + 2][arow] = av.z; As[akq * 4 + 3][arow] = av.w;
        *(float4*)&Bs[brow][bnq * 4] = *(const float4*)(Bp + (size_t)k0 * D_DIM);
        __syncthreads();
#pragma unroll
        for (int kk = 0; kk < 16; kk++) {
            float4 a4 = *(const float4*)&As[kk][ty * 4];
            float4 b4 = *(const float4*)&Bs[kk][tx * 4];
            float ar[4] = {a4.x, a4.y, a4.z, a4.w};
            float br[4] = {b4.x, b4.y, b4.z, b4.w};
#pragma unroll
            for (int i = 0; i < 4; i++)
#pragma unroll
                for (int j = 0; j < 4; j++)
                    acc[i][j] = fmaf(ar[i], br[j], acc[i][j]);
        }
        __syncthreads();
    }
#pragma unroll
    for (int i = 0; i < 4; i++) {
        int row = m0 + ty * 4 + i;
        float sc = g_sgate[row];
#pragma unroll
        for (int j = 0; j < 4; j++)
            out[(size_t)row * D_DIM + n0 + tx * 4 + j] = sc * acc[i][j];
    }
}

// ---------------- Expert path ----------------
__global__ __launch_bounds__(256) void expert_up_kernel(
        const float* __restrict__ x,
        const float* __restrict__ eg,
        const float* __restrict__ eu) {
    int e = blockIdx.z;
    int n = g_cnt[e];
    int m0 = blockIdx.y * 64;
    if (m0 >= n) return;
    int n0 = blockIdx.x * 64;
    const float* Bg = eg + (size_t)e * D_DIM * IMOE;
    const float* Bu = eu + (size_t)e * D_DIM * IMOE;
    __shared__ float As[16][64], Bgs[16][64], Bus[16][64];
    int tid = threadIdx.x;
    int tx = tid & 15, ty = tid >> 4;
    int arow = tid >> 2, akq = tid & 3;
    int brow = tid >> 4, bnq = tid & 15;
    bool avalid = (m0 + arow) < n;
    int tokA = avalid ? g_tok[e * T_TOK + m0 + arow] : 0;
    const float* Ap  = x + (size_t)tokA * D_DIM + akq * 4;
    const float* Bgp = Bg + (size_t)brow * IMOE + n0 + bnq * 4;
    const float* Bup = Bu + (size_t)brow * IMOE + n0 + bnq * 4;
    float accG[4][4], accU[4][4];
#pragma unroll
    for (int i = 0; i < 4; i++)
#pragma unroll
        for (int j = 0; j < 4; j++) { accG[i][j] = 0.f; accU[i][j] = 0.f; }

    for (int k0 = 0; k0 < D_DIM; k0 += 16) {
        float4 av = avalid ? *(const float4*)(Ap + k0) : make_float4(0.f, 0.f, 0.f, 0.f);
        As[akq * 4 + 0][arow] = av.x; As[akq * 4 + 1][arow] = av.y;
        As[akq * 4 + 2][arow] = av.z; As[akq * 4 + 3][arow] = av.w;
        *(float4*)&Bgs[brow][bnq * 4] = *(const float4*)(Bgp + (size_t)k0 * IMOE);
        *(float4*)&Bus[brow][bnq * 4] = *(const float4*)(Bup + (size_t)k0 * IMOE);
        __syncthreads();
#pragma unroll
        for (int kk = 0; kk < 16; kk++) {
            float4 a4 = *(const float4*)&As[kk][ty * 4];
            float4 g4 = *(const float4*)&Bgs[kk][tx * 4];
            float4 u4 = *(const float4*)&Bus[kk][tx * 4];
            float ar[4] = {a4.x, a4.y, a4.z, a4.w};
            float gr[4] = {g4.x, g4.y, g4.z, g4.w};
            float ur[4] = {u4.x, u4.y, u4.z, u4.w};
#pragma unroll
            for (int i = 0; i < 4; i++)
#pragma unroll
                for (int j = 0; j < 4; j++) {
                    accG[i][j] = fmaf(ar[i], gr[j], accG[i][j]);
                    accU[i][j] = fmaf(ar[i], ur[j], accU[i][j]);
                }
        }
        __syncthreads();
    }
    float* H = g_he + (size_t)e * T_TOK * IMOE;
#pragma unroll
    for (int i = 0; i < 4; i++) {
        int row = m0 + ty * 4 + i;
        if (row < n) {
#pragma unroll
            for (int j = 0; j < 4; j++) {
                float g = accG[i][j], u = accU[i][j];
                float h = (g / (1.f + expf(-g))) * u;
                H[(size_t)row * IMOE + n0 + tx * 4 + j] = h;
            }
        }
    }
}

__global__ __launch_bounds__(256) void expert_down_kernel(
        const float* __restrict__ ed,
        float* __restrict__ out) {
    int e = blockIdx.z;
    int n = g_cnt[e];
    int m0 = blockIdx.y * 64;
    if (m0 >= n) return;
    int n0 = blockIdx.x * 64;
    const float* A = g_he + (size_t)e * T_TOK * IMOE;
    const float* B = ed + (size_t)e * IMOE * D_DIM;
    __shared__ float As[16][64], Bs[16][64];
    int tid = threadIdx.x;
    int tx = tid & 15, ty = tid >> 4;
    int arow = tid >> 2, akq = tid & 3;
    int brow = tid >> 4, bnq = tid & 15;
    bool avalid = (m0 + arow) < n;
    const float* Ap = A + (size_t)(avalid ? (m0 + arow) : 0) * IMOE + akq * 4;
    const float* Bp = B + (size_t)brow * D_DIM + n0 + bnq * 4;
    float acc[4][4];
#pragma unroll
    for (int i = 0; i < 4; i++)
#pragma unroll
        for (int j = 0; j < 4; j++) acc[i][j] = 0.f;

    for (int k0 = 0; k0 < IMOE; k0 += 16) {
        float4 av = avalid ? *(const float4*)(Ap + k0) : make_float4(0.f, 0.f, 0.f, 0.f);
        As[akq * 4 + 0][arow] = av.x; As[akq * 4 + 1][arow] = av.y;
        As[akq * 4 + 2][arow] = av.z; As[akq * 4 + 3][arow] = av.w;
        *(float4*)&Bs[brow][bnq * 4] = *(const float4*)(Bp + (size_t)k0 * D_DIM);
        __syncthreads();
#pragma unroll
        for (int kk = 0; kk < 16; kk++) {
            float4 a4 = *(const float4*)&As[kk][ty * 4];
            float4 b4 = *(const float4*)&Bs[kk][tx * 4];
            float ar[4] = {a4.x, a4.y, a4.z, a4.w};
            float br[4] = {b4.x, b4.y, b4.z, b4.w};
#pragma unroll
            for (int i = 0; i < 4; i++)
#pragma unroll
                for (int j = 0; j < 4; j++)
                    acc[i][j] = fmaf(ar[i], br[j], acc[i][j]);
        }
        __syncthreads();
    }
#pragma unroll
    for (int i = 0; i < 4; i++) {
        int row = m0 + ty * 4 + i;
        if (row < n) {
            int tok = g_tok[e * T_TOK + row];
            float w = g_wt[e * T_TOK + row];
#pragma unroll
            for (int j = 0; j < 4; j++)
                atomicAdd(&out[(size_t)tok * D_DIM + n0 + tx * 4 + j], w * acc[i][j]);
        }
    }
}

extern "C" void kernel_launch(void* const* d_in, const int* in_sizes, int n_in,
                              void* d_out, int out_size) {
    const float* x   = (const float*)d_in[0];
    const float* gw  = (const float*)d_in[1];
    const float* eg  = (const float*)d_in[2];
    const float* eu  = (const float*)d_in[3];
    const float* ed  = (const float*)d_in[4];
    const float* sg  = (const float*)d_in[5];
    const float* su  = (const float*)d_in[6];
    const float* sd  = (const float*)d_in[7];
    const float* sgw = (const float*)d_in[8];
    (void)in_sizes; (void)n_in;

    float* out    = (float*)d_out;
    float* logits = out + ((size_t)out_size - (size_t)T_TOK * E_NUM);

    zero_counts_kernel<<<1, 32>>>();
    router_kernel<<<T_TOK / 8, 256>>>(x, gw, sgw, logits);
    // Shared expert (also fully initializes `out` via plain stores)
    shared_up_kernel<<<dim3(ISH / 64, T_TOK / 64), 256>>>(x, sg, su);
    shared_down_kernel<<<dim3(D_DIM / 64, T_TOK / 64), 256>>>(sd, out);
    // Routed experts (atomicAdd on top of shared output)
    expert_up_kernel<<<dim3(IMOE / 64, T_TOK / 64, E_NUM), 256>>>(x, eg, eu);
    expert_down_kernel<<<dim3(D_DIM / 64, T_TOK / 64, E_NUM), 256>>>(ed, out);
}

// round 7
// speedup vs baseline: 2.7320x; 2.7320x over previous
#include <cuda_runtime.h>
#include <cuda_bf16.h>
#include <math.h>
#include <stdint.h>

#define T_TOK 8192
#define D_DIM 1024
#define E_NUM 8
#define IMOE  1024
#define ISH   4096

// ---------------- scratch (device globals; .bss is zero-initialized) ----------------
__device__ __align__(256) __nv_bfloat16 g_xh[(size_t)T_TOK * D_DIM];
__device__ __align__(256) __nv_bfloat16 g_xl[(size_t)T_TOK * D_DIM];
__device__ __align__(256) __nv_bfloat16 g_sgT_h[(size_t)ISH * D_DIM];
__device__ __align__(256) __nv_bfloat16 g_sgT_l[(size_t)ISH * D_DIM];
__device__ __align__(256) __nv_bfloat16 g_suT_h[(size_t)ISH * D_DIM];
__device__ __align__(256) __nv_bfloat16 g_suT_l[(size_t)ISH * D_DIM];
__device__ __align__(256) __nv_bfloat16 g_sdT_h[(size_t)D_DIM * ISH];
__device__ __align__(256) __nv_bfloat16 g_sdT_l[(size_t)D_DIM * ISH];
__device__ __align__(256) __nv_bfloat16 g_egT_h[(size_t)E_NUM * IMOE * D_DIM];
__device__ __align__(256) __nv_bfloat16 g_egT_l[(size_t)E_NUM * IMOE * D_DIM];
__device__ __align__(256) __nv_bfloat16 g_euT_h[(size_t)E_NUM * IMOE * D_DIM];
__device__ __align__(256) __nv_bfloat16 g_euT_l[(size_t)E_NUM * IMOE * D_DIM];
__device__ __align__(256) __nv_bfloat16 g_edT_h[(size_t)E_NUM * D_DIM * IMOE];
__device__ __align__(256) __nv_bfloat16 g_edT_l[(size_t)E_NUM * D_DIM * IMOE];
__device__ __align__(256) __nv_bfloat16 g_hshh[(size_t)T_TOK * ISH];
__device__ __align__(256) __nv_bfloat16 g_hshl[(size_t)T_TOK * ISH];
__device__ __align__(256) __nv_bfloat16 g_heh[(size_t)E_NUM * T_TOK * IMOE];
__device__ __align__(256) __nv_bfloat16 g_hel[(size_t)E_NUM * T_TOK * IMOE];
// fp32 GEMM outputs (expert capacity 64M elems >= shared 32M)
__device__ __align__(256) float g_G[(size_t)E_NUM * T_TOK * IMOE];
__device__ __align__(256) float g_U[(size_t)E_NUM * T_TOK * IMOE];

__device__ int   g_cnt[E_NUM];
__device__ int   g_tok[E_NUM * T_TOK];
__device__ float g_wt [E_NUM * T_TOK];
__device__ float g_sgate[T_TOK];

// ---------------- helpers (sm_80+ ISA only: valid on plain sm_103 target) ----------------
__device__ __forceinline__ uint32_t smem_u32(const void* p) {
    return (uint32_t)__cvta_generic_to_shared(p);
}
__device__ __forceinline__ void cp16(uint32_t dst, const void* src) {
    asm volatile("cp.async.cg.shared.global [%0], [%1], 16;" :: "r"(dst), "l"(src));
}
#define CP_COMMIT() asm volatile("cp.async.commit_group;")
#define CP_WAIT1()  asm volatile("cp.async.wait_group 1;")
__device__ __forceinline__ void ldm_x4(uint32_t* r, uint32_t addr) {
    asm volatile("ldmatrix.sync.aligned.m8n8.x4.shared.b16 {%0,%1,%2,%3}, [%4];"
                 : "=r"(r[0]), "=r"(r[1]), "=r"(r[2]), "=r"(r[3]) : "r"(addr));
}
__device__ __forceinline__ void mma_bf16(float* d, const uint32_t* a, const uint32_t* b) {
    asm volatile("mma.sync.aligned.m16n8k16.row.col.f32.bf16.bf16.f32 "
                 "{%0,%1,%2,%3}, {%4,%5,%6,%7}, {%8,%9}, {%0,%1,%2,%3};"
                 : "+f"(d[0]), "+f"(d[1]), "+f"(d[2]), "+f"(d[3])
                 : "r"(a[0]), "r"(a[1]), "r"(a[2]), "r"(a[3]), "r"(b[0]), "r"(b[1]));
}
__device__ __forceinline__ void bf_split(float v, __nv_bfloat16& h, __nv_bfloat16& l) {
    h = __float2bfloat16(v);
    l = __float2bfloat16(v - __bfloat162float(h));
}

// ---------------- routing ----------------
__global__ void zero_counts_kernel() {
    if (threadIdx.x < E_NUM) g_cnt[threadIdx.x] = 0;
}

__global__ void router_kernel(const float* __restrict__ x,
                              const float* __restrict__ gw,
                              const float* __restrict__ sgw,
                              float* __restrict__ logits_out) {
    int t = (int)((blockIdx.x * blockDim.x + threadIdx.x) >> 5);
    int lane = threadIdx.x & 31;
    if (t >= T_TOK) return;
    const float* xr = x + (size_t)t * D_DIM;
    float acc[E_NUM];
#pragma unroll
    for (int e = 0; e < E_NUM; e++) acc[e] = 0.f;
    float sg = 0.f;
    for (int k = lane; k < D_DIM; k += 32) {
        float xv = xr[k];
#pragma unroll
        for (int e = 0; e < E_NUM; e++) acc[e] = fmaf(xv, gw[k * E_NUM + e], acc[e]);
        sg = fmaf(xv, sgw[k], sg);
    }
#pragma unroll
    for (int o = 16; o; o >>= 1) {
#pragma unroll
        for (int e = 0; e < E_NUM; e++) acc[e] += __shfl_xor_sync(0xffffffffu, acc[e], o);
        sg += __shfl_xor_sync(0xffffffffu, sg, o);
    }
    if (lane == 0) {
        float m = acc[0];
#pragma unroll
        for (int e = 1; e < E_NUM; e++) m = fmaxf(m, acc[e]);
        float p[E_NUM];
#pragma unroll
        for (int e = 0; e < E_NUM; e++) {
            p[e] = expf(acc[e] - m);
            logits_out[t * E_NUM + e] = acc[e];
        }
        int i0 = 0;
#pragma unroll
        for (int e = 1; e < E_NUM; e++) if (p[e] > p[i0]) i0 = e;
        int i1 = -1;
        float best = -1.f;
#pragma unroll
        for (int e = 0; e < E_NUM; e++) {
            if (e == i0) continue;
            if (p[e] > best) { best = p[e]; i1 = e; }
        }
        float s = p[i0] + p[i1];
        float w0 = p[i0] / s, w1 = p[i1] / s;
        int p0 = atomicAdd(&g_cnt[i0], 1);
        g_tok[i0 * T_TOK + p0] = t; g_wt[i0 * T_TOK + p0] = w0;
        int p1 = atomicAdd(&g_cnt[i1], 1);
        g_tok[i1 * T_TOK + p1] = t; g_wt[i1 * T_TOK + p1] = w1;
        g_sgate[t] = 1.f / (1.f + expf(-sg));
    }
}

// ---------------- conversions ----------------
__global__ void split_x_kernel(const float* __restrict__ x,
                               __nv_bfloat16* __restrict__ oh,
                               __nv_bfloat16* __restrict__ ol) {
    size_t i = (size_t)blockIdx.x * blockDim.x + threadIdx.x;  // per float4
    float4 v = reinterpret_cast<const float4*>(x)[i];
    __nv_bfloat16 h[4], l[4];
    bf_split(v.x, h[0], l[0]); bf_split(v.y, h[1], l[1]);
    bf_split(v.z, h[2], l[2]); bf_split(v.w, h[3], l[3]);
    uint2 ph, pl;
    ph.x = ((uint32_t)__bfloat16_as_ushort(h[1]) << 16) | __bfloat16_as_ushort(h[0]);
    ph.y = ((uint32_t)__bfloat16_as_ushort(h[3]) << 16) | __bfloat16_as_ushort(h[2]);
    pl.x = ((uint32_t)__bfloat16_as_ushort(l[1]) << 16) | __bfloat16_as_ushort(l[0]);
    pl.y = ((uint32_t)__bfloat16_as_ushort(l[3]) << 16) | __bfloat16_as_ushort(l[2]);
    reinterpret_cast<uint2*>(oh)[i] = ph;
    reinterpret_cast<uint2*>(ol)[i] = pl;
}

// in [b][K][N] fp32 -> out hi/lo [b][N][K] bf16
__global__ void tsplit_kernel(const float* __restrict__ in,
                              __nv_bfloat16* __restrict__ oh,
                              __nv_bfloat16* __restrict__ ol,
                              int K, int N) {
    __shared__ float t[32][33];
    size_t boff = (size_t)blockIdx.z * K * N;
    in += boff; oh += boff; ol += boff;
    int n0 = blockIdx.x * 32, k0 = blockIdx.y * 32;
    int tx = threadIdx.x, ty = threadIdx.y;
#pragma unroll
    for (int i = 0; i < 4; i++)
        t[ty + i * 8][tx] = in[(size_t)(k0 + ty + i * 8) * N + n0 + tx];
    __syncthreads();
#pragma unroll
    for (int i = 0; i < 4; i++) {
        float v = t[tx][ty + i * 8];
        __nv_bfloat16 h, l;
        bf_split(v, h, l);
        size_t o = (size_t)(n0 + ty + i * 8) * K + k0 + tx;
        oh[o] = h; ol[o] = l;
    }
}

// ---------------- bf16x3 warp-MMA GEMM ----------------
// C[128 x 128] per block, K-tile 32, 8 warps (warp tile 64x32), cp.async double buffer.
// SMEM per stage: Ah,Al,Bh,Bl tiles, each 128 rows x 80B (32 bf16 + pad) = 10240B.
#define TILE_B   10240
#define STAGE_B  40960
#define GEMM_SMEM (2 * STAGE_B)

// epi: 0 = store fp32 C, 1 = sgate*acc store (shared down), 2 = atomicAdd(out[tok], wt*acc)
__global__ __launch_bounds__(256) void mma_gemm(
        const __nv_bfloat16* __restrict__ Ah_, const __nv_bfloat16* __restrict__ Al_,
        const __nv_bfloat16* __restrict__ Bh_, const __nv_bfloat16* __restrict__ Bl_,
        float* __restrict__ C_,
        int lda, int ldb, int ldc, int kchunks,
        int gather, int epi, int expertM,
        long long astrE, long long bstrE, long long cstrE) {
    extern __shared__ char dsm[];
    __shared__ int tok_s[128];
    const int tid = threadIdx.x, wid = tid >> 5, lane = tid & 31;
    const int m0 = blockIdx.y * 128, n0 = blockIdx.x * 128;
    const int e = blockIdx.z;
    int nrows = T_TOK;
    const int* tokp = nullptr;
    const float* wtp = nullptr;
    const __nv_bfloat16 *Ah = Ah_, *Al = Al_, *Bh = Bh_, *Bl = Bl_;
    float* C = C_;
    if (expertM) {
        nrows = g_cnt[e];
        if (m0 >= nrows) return;
        tokp = g_tok + e * T_TOK;
        wtp  = g_wt  + e * T_TOK;
        Ah += astrE * e; Al += astrE * e;
        Bh += bstrE * e; Bl += bstrE * e;
        C  += cstrE * e;
    }
    if (tid < 128) {
        int row = m0 + tid;
        int ar = row;
        if (expertM && gather) ar = tokp[row < nrows ? row : nrows - 1];
        tok_s[tid] = ar;
    }
    __syncthreads();

    // per-thread cp.async geometry: chunks tid and tid+256 of 512 per tile
    const int r0 = tid >> 2;          // 0..63
    const int r1 = r0 + 64;           // 64..127
    const int c16 = tid & 3;          // 16B column within 64B row
    const int a0 = tok_s[r0], a1 = tok_s[r1];
    const __nv_bfloat16* pAh0 = Ah + (size_t)a0 * lda + c16 * 8;
    const __nv_bfloat16* pAh1 = Ah + (size_t)a1 * lda + c16 * 8;
    const __nv_bfloat16* pAl0 = Al + (size_t)a0 * lda + c16 * 8;
    const __nv_bfloat16* pAl1 = Al + (size_t)a1 * lda + c16 * 8;
    const __nv_bfloat16* pBh0 = Bh + (size_t)(n0 + r0) * ldb + c16 * 8;
    const __nv_bfloat16* pBh1 = Bh + (size_t)(n0 + r1) * ldb + c16 * 8;
    const __nv_bfloat16* pBl0 = Bl + (size_t)(n0 + r0) * ldb + c16 * 8;
    const __nv_bfloat16* pBl1 = Bl + (size_t)(n0 + r1) * ldb + c16 * 8;
    const uint32_t sbase = smem_u32(dsm);
    const uint32_t d0 = r0 * 80 + c16 * 16;
    const uint32_t d1 = r1 * 80 + c16 * 16;

    float acc[4][4][4];
#pragma unroll
    for (int mi = 0; mi < 4; mi++)
#pragma unroll
        for (int ni = 0; ni < 4; ni++)
#pragma unroll
            for (int q = 0; q < 4; q++) acc[mi][ni][q] = 0.f;

    const int wm = wid & 1, wn = wid >> 1;
    const uint32_t a_loff = (lane & 15) * 80 + (lane >> 4) * 16;
    const uint32_t b_loff = (((lane >> 4) & 1) * 8 + (lane & 7)) * 80 + ((lane >> 3) & 1) * 16;

    // prologue: stage 0
    {
        uint32_t sb = sbase;
        cp16(sb + d0, pAh0); cp16(sb + d1, pAh1);
        cp16(sb + TILE_B + d0, pAl0); cp16(sb + TILE_B + d1, pAl1);
        cp16(sb + 2 * TILE_B + d0, pBh0); cp16(sb + 2 * TILE_B + d1, pBh1);
        cp16(sb + 3 * TILE_B + d0, pBl0); cp16(sb + 3 * TILE_B + d1, pBl1);
    }
    CP_COMMIT();

    for (int ch = 0; ch < kchunks; ch++) {
        if (ch + 1 < kchunks) {
            int k1 = (ch + 1) * 32;
            uint32_t sb = sbase + ((ch + 1) & 1) * STAGE_B;
            cp16(sb + d0, pAh0 + k1); cp16(sb + d1, pAh1 + k1);
            cp16(sb + TILE_B + d0, pAl0 + k1); cp16(sb + TILE_B + d1, pAl1 + k1);
            cp16(sb + 2 * TILE_B + d0, pBh0 + k1); cp16(sb + 2 * TILE_B + d1, pBh1 + k1);
            cp16(sb + 3 * TILE_B + d0, pBl0 + k1); cp16(sb + 3 * TILE_B + d1, pBl1 + k1);
        }
        CP_COMMIT();
        CP_WAIT1();
        __syncthreads();

        uint32_t st = sbase + (ch & 1) * STAGE_B;
        uint32_t sAh = st, sAl = st + TILE_B, sBh = st + 2 * TILE_B, sBl = st + 3 * TILE_B;
#pragma unroll
        for (int kk = 0; kk < 2; kk++) {
            uint32_t ah[4][4], al[4][4], bh[4][2], bl[4][2];
            uint32_t ak = a_loff + kk * 32;
            uint32_t bk = b_loff + kk * 32;
#pragma unroll
            for (int mi = 0; mi < 4; mi++) {
                uint32_t ro = (wm * 64 + mi * 16) * 80;
                ldm_x4(ah[mi], sAh + ro + ak);
                ldm_x4(al[mi], sAl + ro + ak);
            }
#pragma unroll
            for (int nj = 0; nj < 2; nj++) {
                uint32_t ro = (wn * 32 + nj * 16) * 80;
                uint32_t t4[4];
                ldm_x4(t4, sBh + ro + bk);
                bh[2 * nj][0] = t4[0]; bh[2 * nj][1] = t4[1];
                bh[2 * nj + 1][0] = t4[2]; bh[2 * nj + 1][1] = t4[3];
                ldm_x4(t4, sBl + ro + bk);
                bl[2 * nj][0] = t4[0]; bl[2 * nj][1] = t4[1];
                bl[2 * nj + 1][0] = t4[2]; bl[2 * nj + 1][1] = t4[3];
            }
#pragma unroll
            for (int mi = 0; mi < 4; mi++)
#pragma unroll
                for (int ni = 0; ni < 4; ni++) {
                    mma_bf16(acc[mi][ni], ah[mi], bh[ni]);
                    mma_bf16(acc[mi][ni], ah[mi], bl[ni]);
                    mma_bf16(acc[mi][ni], al[mi], bh[ni]);
                }
        }
        __syncthreads();
    }

    // epilogue
    const int rb = m0 + wm * 64, cb = n0 + wn * 32;
#pragma unroll
    for (int mi = 0; mi < 4; mi++) {
        int ra = rb + mi * 16 + (lane >> 2);
        int rc = ra + 8;
        if (epi == 1) {
            float s0 = g_sgate[ra], s1 = g_sgate[rc];
#pragma unroll
            for (int ni = 0; ni < 4; ni++) {
                int c = cb + ni * 8 + 2 * (lane & 3);
                float* d = acc[mi][ni];
                *(float2*)&C[(size_t)ra * ldc + c] = make_float2(s0 * d[0], s0 * d[1]);
                *(float2*)&C[(size_t)rc * ldc + c] = make_float2(s1 * d[2], s1 * d[3]);
            }
        } else if (epi == 0) {
            bool v0 = !expertM || ra < nrows;
            bool v1 = !expertM || rc < nrows;
#pragma unroll
            for (int ni = 0; ni < 4; ni++) {
                int c = cb + ni * 8 + 2 * (lane & 3);
                float* d = acc[mi][ni];
                if (v0) *(float2*)&C[(size_t)ra * ldc + c] = make_float2(d[0], d[1]);
                if (v1) *(float2*)&C[(size_t)rc * ldc + c] = make_float2(d[2], d[3]);
            }
        } else {
            bool v0 = ra < nrows, v1 = rc < nrows;
            int t0 = 0, t1 = 0; float w0 = 0.f, w1 = 0.f;
            if (v0) { t0 = tokp[ra]; w0 = wtp[ra]; }
            if (v1) { t1 = tokp[rc]; w1 = wtp[rc]; }
#pragma unroll
            for (int ni = 0; ni < 4; ni++) {
                int c = cb + ni * 8 + 2 * (lane & 3);
                float* d = acc[mi][ni];
                if (v0) {
                    atomicAdd(&C[(size_t)t0 * ldc + c],     w0 * d[0]);
                    atomicAdd(&C[(size_t)t0 * ldc + c + 1], w0 * d[1]);
                }
                if (v1) {
                    atomicAdd(&C[(size_t)t1 * ldc + c],     w1 * d[2]);
                    atomicAdd(&C[(size_t)t1 * ldc + c + 1], w1 * d[3]);
                }
            }
        }
    }
}

// ---------------- SiLU + bf16 split: H = silu(G)*U ----------------
__global__ void silu_kernel(const float* __restrict__ G, const float* __restrict__ U,
                            __nv_bfloat16* __restrict__ Hh, __nv_bfloat16* __restrict__ Hl,
                            int N, int expertM) {
    int e = blockIdx.z;
    int row = blockIdx.y;
    if (expertM && row >= g_cnt[e]) return;
    size_t base = ((size_t)e * T_TOK + row) * N + blockIdx.x * 1024 + threadIdx.x * 4;
    float4 g4 = *(const float4*)(G + base);
    float4 u4 = *(const float4*)(U + base);
    float h[4];
    h[0] = (g4.x / (1.f + __expf(-g4.x))) * u4.x;
    h[1] = (g4.y / (1.f + __expf(-g4.y))) * u4.y;
    h[2] = (g4.z / (1.f + __expf(-g4.z))) * u4.z;
    h[3] = (g4.w / (1.f + __expf(-g4.w))) * u4.w;
    __nv_bfloat16 hh[4], hl[4];
#pragma unroll
    for (int i = 0; i < 4; i++) bf_split(h[i], hh[i], hl[i]);
    uint2 ph, pl;
    ph.x = ((uint32_t)__bfloat16_as_ushort(hh[1]) << 16) | __bfloat16_as_ushort(hh[0]);
    ph.y = ((uint32_t)__bfloat16_as_ushort(hh[3]) << 16) | __bfloat16_as_ushort(hh[2]);
    pl.x = ((uint32_t)__bfloat16_as_ushort(hl[1]) << 16) | __bfloat16_as_ushort(hl[0]);
    pl.y = ((uint32_t)__bfloat16_as_ushort(hl[3]) << 16) | __bfloat16_as_ushort(hl[2]);
    *(uint2*)(Hh + base) = ph;
    *(uint2*)(Hl + base) = pl;
}

// ---------------- launch ----------------
extern "C" void kernel_launch(void* const* d_in, const int* in_sizes, int n_in,
                              void* d_out, int out_size) {
    const float* x   = (const float*)d_in[0];
    const float* gw  = (const float*)d_in[1];
    const float* eg  = (const float*)d_in[2];
    const float* eu  = (const float*)d_in[3];
    const float* ed  = (const float*)d_in[4];
    const float* sg  = (const float*)d_in[5];
    const float* su  = (const float*)d_in[6];
    const float* sd  = (const float*)d_in[7];
    const float* sgw = (const float*)d_in[8];
    (void)in_sizes; (void)n_in;

    float* out    = (float*)d_out;
    float* logits = out + ((size_t)out_size - (size_t)T_TOK * E_NUM);

    static int smem_set = 0;
    if (!smem_set) {
        cudaFuncSetAttribute(mma_gemm, cudaFuncAttributeMaxDynamicSharedMemorySize, GEMM_SMEM);
        smem_set = 1;
    }

    __nv_bfloat16 *xh, *xl, *sgh, *sgl, *suh, *sul, *sdh, *sdl;
    __nv_bfloat16 *egh, *egl, *euh, *eul, *edh, *edl, *hsh, *hsl, *heh, *hel;
    float *gG, *gU;
    cudaGetSymbolAddress((void**)&xh,  g_xh);    cudaGetSymbolAddress((void**)&xl,  g_xl);
    cudaGetSymbolAddress((void**)&sgh, g_sgT_h); cudaGetSymbolAddress((void**)&sgl, g_sgT_l);
    cudaGetSymbolAddress((void**)&suh, g_suT_h); cudaGetSymbolAddress((void**)&sul, g_suT_l);
    cudaGetSymbolAddress((void**)&sdh, g_sdT_h); cudaGetSymbolAddress((void**)&sdl, g_sdT_l);
    cudaGetSymbolAddress((void**)&egh, g_egT_h); cudaGetSymbolAddress((void**)&egl, g_egT_l);
    cudaGetSymbolAddress((void**)&euh, g_euT_h); cudaGetSymbolAddress((void**)&eul, g_euT_l);
    cudaGetSymbolAddress((void**)&edh, g_edT_h); cudaGetSymbolAddress((void**)&edl, g_edT_l);
    cudaGetSymbolAddress((void**)&hsh, g_hshh);  cudaGetSymbolAddress((void**)&hsl, g_hshl);
    cudaGetSymbolAddress((void**)&heh, g_heh);   cudaGetSymbolAddress((void**)&hel, g_hel);
    cudaGetSymbolAddress((void**)&gG,  g_G);     cudaGetSymbolAddress((void**)&gU,  g_U);

    zero_counts_kernel<<<1, 32>>>();
    router_kernel<<<T_TOK / 8, 256>>>(x, gw, sgw, logits);

    // conversions to bf16 hi/lo (weights transposed to [N][K])
    split_x_kernel<<<(T_TOK * D_DIM / 4) / 256, 256>>>(x, xh, xl);
    dim3 tb(32, 8);
    tsplit_kernel<<<dim3(ISH / 32, D_DIM / 32, 1), tb>>>(sg, sgh, sgl, D_DIM, ISH);
    tsplit_kernel<<<dim3(ISH / 32, D_DIM / 32, 1), tb>>>(su, suh, sul, D_DIM, ISH);
    tsplit_kernel<<<dim3(D_DIM / 32, ISH / 32, 1), tb>>>(sd, sdh, sdl, ISH, D_DIM);
    tsplit_kernel<<<dim3(IMOE / 32, D_DIM / 32, E_NUM), tb>>>(eg, egh, egl, D_DIM, IMOE);
    tsplit_kernel<<<dim3(IMOE / 32, D_DIM / 32, E_NUM), tb>>>(eu, euh, eul, D_DIM, IMOE);
    tsplit_kernel<<<dim3(D_DIM / 32, IMOE / 32, E_NUM), tb>>>(ed, edh, edl, IMOE, D_DIM);

    // ---- shared expert ----
    mma_gemm<<<dim3(ISH / 128, T_TOK / 128, 1), 256, GEMM_SMEM>>>(
        xh, xl, sgh, sgl, gG, D_DIM, D_DIM, ISH, D_DIM / 32, 0, 0, 0, 0, 0, 0);
    mma_gemm<<<dim3(ISH / 128, T_TOK / 128, 1), 256, GEMM_SMEM>>>(
        xh, xl, suh, sul, gU, D_DIM, D_DIM, ISH, D_DIM / 32, 0, 0, 0, 0, 0, 0);
    silu_kernel<<<dim3(ISH / 1024, T_TOK, 1), 256>>>(gG, gU, hsh, hsl, ISH, 0);
    mma_gemm<<<dim3(D_DIM / 128, T_TOK / 128, 1), 256, GEMM_SMEM>>>(
        hsh, hsl, sdh, sdl, out, ISH, ISH, D_DIM, ISH / 32, 0, 1, 0, 0, 0, 0);

    // ---- routed experts ----
    mma_gemm<<<dim3(IMOE / 128, T_TOK / 128, E_NUM), 256, GEMM_SMEM>>>(
        xh, xl, egh, egl, gG, D_DIM, D_DIM, IMOE, D_DIM / 32, 1, 0, 1,
        0, (long long)IMOE * D_DIM, (long long)T_TOK * IMOE);
    mma_gemm<<<dim3(IMOE / 128, T_TOK / 128, E_NUM), 256, GEMM_SMEM>>>(
        xh, xl, euh, eul, gU, D_DIM, D_DIM, IMOE, D_DIM / 32, 1, 0, 1,
        0, (long long)IMOE * D_DIM, (long long)T_TOK * IMOE);
    silu_kernel<<<dim3(IMOE / 1024, T_TOK, E_NUM), 256>>>(gG, gU, heh, hel, IMOE, 1);
    mma_gemm<<<dim3(D_DIM / 128, T_TOK / 128, E_NUM), 256, GEMM_SMEM>>>(
        heh, hel, edh, edl, out, IMOE, IMOE, D_DIM, IMOE / 32, 0, 2, 1,
        (long long)T_TOK * IMOE, (long long)D_DIM * IMOE, 0);
}